// round 2
// baseline (speedup 1.0000x reference)
#include <cuda_runtime.h>
#include <math.h>

// Problem constants (fixed by the dataset)
#define NMAX   100000
#define CIN    64
#define COUT   64
#define KNB    16
#define DIN    67          // 3 + CIN
#define PTS    16          // points per block
#define THREADS 256

// Scratch for per-node A = [coords, feats] @ W1 + b1  (25.6 MB)
__device__ float g_A[(size_t)NMAX * COUT];

__device__ __forceinline__ float gelu_exact(float x) {
    // 0.5 * x * (1 + erf(x / sqrt(2)))
    return 0.5f * x * (1.0f + erff(x * 0.70710678118654752440f));
}

// ---------------------------------------------------------------------------
// Kernel 1: A[i][c] = sum_d x_i[d] * W1[d][c] + b1[c],  x_i = [coords_i, feat_i]
// One block = 16 points; thread (p, q) computes float4 chunk q of point p.
// ---------------------------------------------------------------------------
__global__ __launch_bounds__(THREADS)
void compute_A_kernel(const float* __restrict__ coords,
                      const float* __restrict__ features,
                      const float* __restrict__ W1,
                      const float* __restrict__ b1,
                      int N) {
    __shared__ float W1s[DIN * COUT];        // 17152 B, flat row-major [j][c]
    __shared__ float xs[PTS][DIN + 1];       // padded rows (stride 68)

    const int t  = threadIdx.x;
    const int i0 = blockIdx.x * PTS;
    const int p  = t >> 4;
    const int q  = t & 15;
    const int i  = i0 + p;

    // W1 -> shared (vectorized: 4288 floats = 1072 float4)
    {
        const float4* src = (const float4*)W1;
        float4* dst = (float4*)W1s;
        #pragma unroll
        for (int e = t; e < (DIN * COUT) / 4; e += THREADS) dst[e] = src[e];
    }
    // features -> xs[p][3..66]
    if (i < N) {
        float4 f = *(const float4*)(features + (size_t)i * CIN + q * 4);
        xs[p][3 + q * 4 + 0] = f.x;
        xs[p][3 + q * 4 + 1] = f.y;
        xs[p][3 + q * 4 + 2] = f.z;
        xs[p][3 + q * 4 + 3] = f.w;
    }
    // coords -> xs[p][0..2]
    if (t < PTS * 3) {
        int pp = t / 3, d = t % 3;
        if (i0 + pp < N) xs[pp][d] = coords[(size_t)(i0 + pp) * 3 + d];
    }
    __syncthreads();

    if (i >= N) return;

    float4 acc = *(const float4*)(b1 + q * 4);
    #pragma unroll
    for (int j = 0; j < DIN; ++j) {
        float xv = xs[p][j];
        float4 w = *(const float4*)(W1s + j * COUT + q * 4);
        acc.x = fmaf(xv, w.x, acc.x);
        acc.y = fmaf(xv, w.y, acc.y);
        acc.z = fmaf(xv, w.z, acc.z);
        acc.w = fmaf(xv, w.w, acc.w);
    }
    *(float4*)(g_A + (size_t)i * COUT + q * 4) = acc;
}

// ---------------------------------------------------------------------------
// Kernel 2: fused gather + GELU + mean + epilogue GEMMs
//   Hbar_i = mean_k gelu(A_{idx[i,k]} + B_i),  B_i = -coords_i @ W1[0:3]
//   out_i  = Hbar_i @ W2 + f_i @ Ws + (b2 + bs)
// ---------------------------------------------------------------------------
__global__ __launch_bounds__(THREADS)
void fused_main_kernel(const float* __restrict__ coords,
                       const float* __restrict__ features,
                       const int* __restrict__ idx,
                       const float* __restrict__ W1,
                       const float* __restrict__ W2,
                       const float* __restrict__ b2,
                       const float* __restrict__ Ws,
                       const float* __restrict__ bs,
                       float* __restrict__ out,
                       int N) {
    __shared__ float W2s[COUT * COUT];          // 16 KB, flat [j][c]
    __shared__ float Wss[CIN * COUT];           // 16 KB, flat [j][c]
    __shared__ int   idxs[PTS][KNB];            // 1 KB
    __shared__ float hbs[PTS][COUT + 4];        // padded stride 68
    __shared__ float fs[PTS][CIN + 4];          // padded stride 68
    __shared__ float cs[PTS][3];

    const int t  = threadIdx.x;
    const int i0 = blockIdx.x * PTS;
    const int p  = t >> 4;
    const int q  = t & 15;
    const int i  = i0 + p;

    // Stage weights (vectorized)
    {
        const float4* s2 = (const float4*)W2;
        const float4* ss = (const float4*)Ws;
        float4* d2 = (float4*)W2s;
        float4* ds = (float4*)Wss;
        #pragma unroll
        for (int e = t; e < (COUT * COUT) / 4; e += THREADS) {
            d2[e] = s2[e];
            ds[e] = ss[e];
        }
    }
    // Stage neighbor indices: thread t loads idx[i0*16 + t]  (int32)
    {
        int ip = i0 + (t >> 4);
        if (ip < N) idxs[t >> 4][t & 15] = idx[(size_t)ip * KNB + (t & 15)];
    }
    // Stage features (also needed for skip GEMM)
    if (i < N) {
        float4 f = *(const float4*)(features + (size_t)i * CIN + q * 4);
        *(float4*)&fs[p][q * 4] = f;   // row base p*272 and offset 16*q are 16B-aligned
    }
    // Stage coords
    if (t < PTS * 3) {
        int pp = t / 3, d = t % 3;
        if (i0 + pp < N) cs[pp][d] = coords[(size_t)(i0 + pp) * 3 + d];
    }
    __syncthreads();

    if (i < N) {
        // B_i chunk: -(c_i . W1[0:3, c4])  (W1 rows 0..2, L2/L1 cached broadcast)
        float4 w0 = __ldg((const float4*)(W1 + 0 * COUT + q * 4));
        float4 w1 = __ldg((const float4*)(W1 + 1 * COUT + q * 4));
        float4 w2 = __ldg((const float4*)(W1 + 2 * COUT + q * 4));
        float cx = cs[p][0], cy = cs[p][1], cz = cs[p][2];
        float4 b4;
        b4.x = -(cx * w0.x + cy * w1.x + cz * w2.x);
        b4.y = -(cx * w0.y + cy * w1.y + cz * w2.y);
        b4.z = -(cx * w0.z + cy * w1.z + cz * w2.z);
        b4.w = -(cx * w0.w + cy * w1.w + cz * w2.w);

        float4 acc = make_float4(0.f, 0.f, 0.f, 0.f);
        #pragma unroll
        for (int k = 0; k < KNB; ++k) {
            int j = idxs[p][k];
            float4 a = *(const float4*)(g_A + (size_t)j * COUT + q * 4);
            acc.x += gelu_exact(a.x + b4.x);
            acc.y += gelu_exact(a.y + b4.y);
            acc.z += gelu_exact(a.z + b4.z);
            acc.w += gelu_exact(a.w + b4.w);
        }
        const float inv = 1.0f / (float)KNB;
        float4 hb = make_float4(acc.x * inv, acc.y * inv, acc.z * inv, acc.w * inv);
        *(float4*)&hbs[p][q * 4] = hb;
    }
    __syncthreads();

    if (i >= N) return;

    float4 o;
    {
        float4 bb2 = __ldg((const float4*)(b2 + q * 4));
        float4 bbs = __ldg((const float4*)(bs + q * 4));
        o = make_float4(bb2.x + bbs.x, bb2.y + bbs.y, bb2.z + bbs.z, bb2.w + bbs.w);
    }
    #pragma unroll
    for (int j = 0; j < COUT; ++j) {
        float h = hbs[p][j];
        float4 wa = *(const float4*)(W2s + j * COUT + q * 4);
        o.x = fmaf(h, wa.x, o.x);
        o.y = fmaf(h, wa.y, o.y);
        o.z = fmaf(h, wa.z, o.z);
        o.w = fmaf(h, wa.w, o.w);
        float fv = fs[p][j];
        float4 wb = *(const float4*)(Wss + j * COUT + q * 4);
        o.x = fmaf(fv, wb.x, o.x);
        o.y = fmaf(fv, wb.y, o.y);
        o.z = fmaf(fv, wb.z, o.z);
        o.w = fmaf(fv, wb.w, o.w);
    }
    *(float4*)(out + (size_t)i * COUT + q * 4) = o;
}

// ---------------------------------------------------------------------------
// Launch
// Inputs (metadata order): coords[N,3] f32, features[N,64] f32, idx[N,16] i32,
//   W1[67,64], b1[64], W2[64,64], b2[64], Ws[64,64], bs[64]  (all f32)
// Output: [N,64] f32
// ---------------------------------------------------------------------------
extern "C" void kernel_launch(void* const* d_in, const int* in_sizes, int n_in,
                              void* d_out, int out_size) {
    const float* coords   = (const float*)d_in[0];
    const float* features = (const float*)d_in[1];
    const int*   idx      = (const int*)d_in[2];
    const float* W1       = (const float*)d_in[3];
    const float* b1       = (const float*)d_in[4];
    const float* W2       = (const float*)d_in[5];
    const float* b2       = (const float*)d_in[6];
    const float* Ws       = (const float*)d_in[7];
    const float* bs       = (const float*)d_in[8];
    float*       out      = (float*)d_out;

    const int N = in_sizes[0] / 3;
    const int blocks = (N + PTS - 1) / PTS;

    compute_A_kernel<<<blocks, THREADS>>>(coords, features, W1, b1, N);
    fused_main_kernel<<<blocks, THREADS>>>(coords, features, idx, W1, W2, b2,
                                           Ws, bs, out, N);
}

// round 3
// speedup vs baseline: 1.2330x; 1.2330x over previous
#include <cuda_runtime.h>
#include <math.h>

// Problem constants (fixed by the dataset)
#define NMAX   100000
#define CIN    64
#define COUT   64
#define KNB    16
#define DIN    67          // 3 + CIN
#define PTS    64          // points per block
#define THREADS 256

typedef unsigned long long u64;

// Scratch for per-node A = [coords, feats] @ W1 + b1  (25.6 MB)
__device__ float g_A[(size_t)NMAX * COUT];

// ---- packed f32x2 helpers (sm_100+) --------------------------------------
__device__ __forceinline__ u64 pack2(float lo, float hi) {
    u64 r; asm("mov.b64 %0, {%1, %2};" : "=l"(r) : "f"(lo), "f"(hi)); return r;
}
__device__ __forceinline__ void unpack2(u64 v, float& lo, float& hi) {
    asm("mov.b64 {%0, %1}, %2;" : "=f"(lo), "=f"(hi) : "l"(v));
}
__device__ __forceinline__ u64 fma2(u64 a, u64 b, u64 c) {
    u64 d; asm("fma.rn.f32x2 %0, %1, %2, %3;" : "=l"(d) : "l"(a), "l"(b), "l"(c));
    return d;
}

__device__ __forceinline__ float gelu_exact(float x) {
    // 0.5 * x * (1 + erf(x / sqrt(2)))  -- exact erf, matches reference
    return 0.5f * x * (1.0f + erff(x * 0.70710678118654752440f));
}

// ---------------------------------------------------------------------------
// Kernel 1: A[i][c] = [coords_i, feat_i] @ W1 + b1
// 64 points / block. Thread (pg, q): 4 points (pg*4..+3) x channel chunk q*4.
// x staged TRANSPOSED in shared so per-j activation load is one LDS.128.
// GEMM inner loop uses packed fma.rn.f32x2.
// ---------------------------------------------------------------------------
__global__ __launch_bounds__(THREADS, 4)
void compute_A_kernel(const float* __restrict__ coords,
                      const float* __restrict__ features,
                      const float* __restrict__ W1,
                      const float* __restrict__ b1,
                      int N) {
    __shared__ float W1s[DIN * COUT];   // [j][c] flat, 17.2 KB
    __shared__ float xsT[DIN][68];      // [j][point], padded, 18.2 KB

    const int t  = threadIdx.x;
    const int i0 = blockIdx.x * PTS;
    const int q  = t & 15;
    const int pg = t >> 4;

    // W1 -> shared
    {
        const float4* src = (const float4*)W1;
        float4* dst = (float4*)W1s;
        for (int e = t; e < (DIN * COUT) / 4; e += THREADS) dst[e] = src[e];
    }
    // features -> xsT rows 3..66 (transposed; coalesced global reads)
    {
        int c  = t & 63;          // feature channel
        int p0 = t >> 6;          // 0..3
        #pragma unroll
        for (int rr = 0; rr < 16; ++rr) {
            int pt = p0 * 16 + rr;
            if (i0 + pt < N)
                xsT[3 + c][pt] = features[(size_t)(i0 + pt) * CIN + c];
        }
    }
    // coords -> xsT rows 0..2
    if (t < PTS * 3) {
        int pt = t / 3, d = t - pt * 3;
        if (i0 + pt < N) xsT[d][pt] = coords[(size_t)(i0 + pt) * 3 + d];
    }
    __syncthreads();

    // accumulators: 4 points x (2 packed pairs of channels)
    u64 accLo[4], accHi[4];
    {
        float4 bb = ((const float4*)b1)[q];
        u64 blo = pack2(bb.x, bb.y), bhi = pack2(bb.z, bb.w);
        #pragma unroll
        for (int r = 0; r < 4; ++r) { accLo[r] = blo; accHi[r] = bhi; }
    }

    #pragma unroll
    for (int j = 0; j < DIN; ++j) {
        float4 w = *(const float4*)(W1s + j * COUT + q * 4);
        u64 wlo = pack2(w.x, w.y), whi = pack2(w.z, w.w);
        float4 xv = *(const float4*)(&xsT[j][pg * 4]);   // 4 points' x_j
        u64 x0 = pack2(xv.x, xv.x);
        u64 x1 = pack2(xv.y, xv.y);
        u64 x2 = pack2(xv.z, xv.z);
        u64 x3 = pack2(xv.w, xv.w);
        accLo[0] = fma2(x0, wlo, accLo[0]);  accHi[0] = fma2(x0, whi, accHi[0]);
        accLo[1] = fma2(x1, wlo, accLo[1]);  accHi[1] = fma2(x1, whi, accHi[1]);
        accLo[2] = fma2(x2, wlo, accLo[2]);  accHi[2] = fma2(x2, whi, accHi[2]);
        accLo[3] = fma2(x3, wlo, accLo[3]);  accHi[3] = fma2(x3, whi, accHi[3]);
    }

    #pragma unroll
    for (int r = 0; r < 4; ++r) {
        int i = i0 + pg * 4 + r;
        if (i < N) {
            float o0, o1, o2, o3;
            unpack2(accLo[r], o0, o1);
            unpack2(accHi[r], o2, o3);
            *(float4*)(g_A + (size_t)i * COUT + q * 4) = make_float4(o0, o1, o2, o3);
        }
    }
}

// ---------------------------------------------------------------------------
// Kernel 2: fused gather + GELU + mean + epilogue GEMMs, 64 points / block.
//   Hbar_i = mean_k gelu(A_{idx[i,k]} + B_i),  B_i = -coords_i @ W1[0:3]
//   out_i  = Hbar_i @ W2 + f_i @ Ws + (b2 + bs)
// Dynamic smem layout (floats): W2s[4096] Wss[4096] hT[64*68] fT[64*68]
//                               cs[192] | idxs[1024] (int)
// ---------------------------------------------------------------------------
#define SM_W2   0
#define SM_WS   4096
#define SM_HT   8192
#define SM_FT   12544
#define SM_CS   16896
#define SM_FLOATS 17088
#define K2_SMEM_BYTES (SM_FLOATS * 4 + 1024 * 4)   // 72448

__global__ __launch_bounds__(THREADS, 2)
void fused_main_kernel(const float* __restrict__ coords,
                       const float* __restrict__ features,
                       const int* __restrict__ idx,
                       const float* __restrict__ W1,
                       const float* __restrict__ W2,
                       const float* __restrict__ b2,
                       const float* __restrict__ Ws,
                       const float* __restrict__ bs,
                       float* __restrict__ out,
                       int N) {
    extern __shared__ float sm2[];
    float* W2s = sm2 + SM_W2;
    float* Wss = sm2 + SM_WS;
    float* hT  = sm2 + SM_HT;    // [channel][point], stride 68
    float* fT  = sm2 + SM_FT;    // [channel][point], stride 68
    float* cs  = sm2 + SM_CS;    // [point][3]
    int*   idxs = (int*)(sm2 + SM_FLOATS);

    const int t  = threadIdx.x;
    const int i0 = blockIdx.x * PTS;
    const int q  = t & 15;
    const int pg = t >> 4;

    // ---- staging -----------------------------------------------------------
    {
        const float4* s2 = (const float4*)W2;
        const float4* ss = (const float4*)Ws;
        float4* d2 = (float4*)W2s;
        float4* ds = (float4*)Wss;
        for (int e = t; e < (COUT * COUT) / 4; e += THREADS) {
            d2[e] = s2[e];
            ds[e] = ss[e];
        }
    }
    // features -> fT transposed (coalesced reads)
    {
        int c  = t & 63;
        int p0 = t >> 6;
        #pragma unroll
        for (int rr = 0; rr < 16; ++rr) {
            int pt = p0 * 16 + rr;
            if (i0 + pt < N)
                fT[c * 68 + pt] = features[(size_t)(i0 + pt) * CIN + c];
            else
                fT[c * 68 + pt] = 0.0f;
        }
    }
    // neighbor indices
    for (int e = t; e < PTS * KNB; e += THREADS) {
        int row = e >> 4;
        idxs[e] = (i0 + row < N) ? idx[(size_t)(i0 + row) * KNB + (e & 15)] : 0;
    }
    // coords
    if (t < PTS * 3) {
        int pt = t / 3, d = t - pt * 3;
        if (i0 + pt < N) cs[pt * 3 + d] = coords[(size_t)(i0 + pt) * 3 + d];
    }
    __syncthreads();

    // ---- phase A: gather + GELU + mean ------------------------------------
    {
        const float4* W1v = (const float4*)W1;
        float4 w0 = __ldg(W1v + 0 * 16 + q);   // W1 row 0, chunk q
        float4 w1 = __ldg(W1v + 1 * 16 + q);   // W1 row 1
        float4 w2 = __ldg(W1v + 2 * 16 + q);   // W1 row 2

        #pragma unroll
        for (int r = 0; r < 4; ++r) {
            int pl = pg * 4 + r;
            int i  = i0 + pl;
            float h0 = 0.f, h1 = 0.f, h2 = 0.f, h3 = 0.f;
            if (i < N) {
                float cx = cs[pl * 3 + 0], cy = cs[pl * 3 + 1], cz = cs[pl * 3 + 2];
                float bx = -(cx * w0.x + cy * w1.x + cz * w2.x);
                float by = -(cx * w0.y + cy * w1.y + cz * w2.y);
                float bz = -(cx * w0.z + cy * w1.z + cz * w2.z);
                float bw = -(cx * w0.w + cy * w1.w + cz * w2.w);
                float a0 = 0.f, a1 = 0.f, a2 = 0.f, a3 = 0.f;
                #pragma unroll
                for (int k = 0; k < KNB; ++k) {
                    int j = idxs[pl * KNB + k];
                    float4 a = *(const float4*)(g_A + (size_t)j * COUT + q * 4);
                    a0 += gelu_exact(a.x + bx);
                    a1 += gelu_exact(a.y + by);
                    a2 += gelu_exact(a.z + bz);
                    a3 += gelu_exact(a.w + bw);
                }
                const float inv = 1.0f / (float)KNB;
                h0 = a0 * inv; h1 = a1 * inv; h2 = a2 * inv; h3 = a3 * inv;
            }
            hT[(q * 4 + 0) * 68 + pl] = h0;
            hT[(q * 4 + 1) * 68 + pl] = h1;
            hT[(q * 4 + 2) * 68 + pl] = h2;
            hT[(q * 4 + 3) * 68 + pl] = h3;
        }
    }
    __syncthreads();

    // ---- phase B: out = Hbar @ W2 + f @ Ws + (b2+bs), packed f32x2 --------
    u64 accLo[4], accHi[4];
    {
        float4 bb2 = __ldg((const float4*)b2 + q);
        float4 bbs = __ldg((const float4*)bs + q);
        u64 olo = pack2(bb2.x + bbs.x, bb2.y + bbs.y);
        u64 ohi = pack2(bb2.z + bbs.z, bb2.w + bbs.w);
        #pragma unroll
        for (int r = 0; r < 4; ++r) { accLo[r] = olo; accHi[r] = ohi; }
    }

    #pragma unroll 8
    for (int j = 0; j < COUT; ++j) {
        float4 wv2 = *(const float4*)(W2s + j * COUT + q * 4);
        float4 wvs = *(const float4*)(Wss + j * COUT + q * 4);
        u64 w2lo = pack2(wv2.x, wv2.y), w2hi = pack2(wv2.z, wv2.w);
        u64 wslo = pack2(wvs.x, wvs.y), wshi = pack2(wvs.z, wvs.w);
        float4 h4 = *(const float4*)(hT + j * 68 + pg * 4);  // 4 points' h_j
        float4 f4 = *(const float4*)(fT + j * 68 + pg * 4);  // 4 points' f_j

        u64 hd, fd;
        hd = pack2(h4.x, h4.x); fd = pack2(f4.x, f4.x);
        accLo[0] = fma2(hd, w2lo, accLo[0]);  accHi[0] = fma2(hd, w2hi, accHi[0]);
        accLo[0] = fma2(fd, wslo, accLo[0]);  accHi[0] = fma2(fd, wshi, accHi[0]);
        hd = pack2(h4.y, h4.y); fd = pack2(f4.y, f4.y);
        accLo[1] = fma2(hd, w2lo, accLo[1]);  accHi[1] = fma2(hd, w2hi, accHi[1]);
        accLo[1] = fma2(fd, wslo, accLo[1]);  accHi[1] = fma2(fd, wshi, accHi[1]);
        hd = pack2(h4.z, h4.z); fd = pack2(f4.z, f4.z);
        accLo[2] = fma2(hd, w2lo, accLo[2]);  accHi[2] = fma2(hd, w2hi, accHi[2]);
        accLo[2] = fma2(fd, wslo, accLo[2]);  accHi[2] = fma2(fd, wshi, accHi[2]);
        hd = pack2(h4.w, h4.w); fd = pack2(f4.w, f4.w);
        accLo[3] = fma2(hd, w2lo, accLo[3]);  accHi[3] = fma2(hd, w2hi, accHi[3]);
        accLo[3] = fma2(fd, wslo, accLo[3]);  accHi[3] = fma2(fd, wshi, accHi[3]);
    }

    #pragma unroll
    for (int r = 0; r < 4; ++r) {
        int i = i0 + pg * 4 + r;
        if (i < N) {
            float o0, o1, o2, o3;
            unpack2(accLo[r], o0, o1);
            unpack2(accHi[r], o2, o3);
            *(float4*)(out + (size_t)i * COUT + q * 4) = make_float4(o0, o1, o2, o3);
        }
    }
}

// ---------------------------------------------------------------------------
// Launch
// Inputs: coords[N,3] f32, features[N,64] f32, idx[N,16] i32,
//   W1[67,64], b1[64], W2[64,64], b2[64], Ws[64,64], bs[64]  (all f32)
// Output: [N,64] f32
// ---------------------------------------------------------------------------
extern "C" void kernel_launch(void* const* d_in, const int* in_sizes, int n_in,
                              void* d_out, int out_size) {
    const float* coords   = (const float*)d_in[0];
    const float* features = (const float*)d_in[1];
    const int*   idx      = (const int*)d_in[2];
    const float* W1       = (const float*)d_in[3];
    const float* b1       = (const float*)d_in[4];
    const float* W2       = (const float*)d_in[5];
    const float* b2       = (const float*)d_in[6];
    const float* Ws       = (const float*)d_in[7];
    const float* bs       = (const float*)d_in[8];
    float*       out      = (float*)d_out;

    const int N = in_sizes[0] / 3;
    const int blocks = (N + PTS - 1) / PTS;

    static int attr_done = 0;
    if (!attr_done) {
        cudaFuncSetAttribute(fused_main_kernel,
                             cudaFuncAttributeMaxDynamicSharedMemorySize,
                             K2_SMEM_BYTES);
        attr_done = 1;
    }

    compute_A_kernel<<<blocks, THREADS>>>(coords, features, W1, b1, N);
    fused_main_kernel<<<blocks, THREADS, K2_SMEM_BYTES>>>(coords, features, idx,
                                                          W1, W2, b2, Ws, bs,
                                                          out, N);
}

// round 6
// speedup vs baseline: 1.4632x; 1.1867x over previous
#include <cuda_runtime.h>
#include <math.h>

// Problem constants (fixed by the dataset)
#define NMAX   100000
#define CIN    64
#define COUT   64
#define KNB    16
#define DIN    67          // 3 + CIN
#define PTS    64          // points per block
#define THREADS 256

typedef unsigned long long u64;

// Scratch for per-node A = [coords, feats] @ W1 + b1  (25.6 MB)
__device__ float g_A[(size_t)NMAX * COUT];

// ---- packed f32x2 helpers (sm_100+) --------------------------------------
__device__ __forceinline__ u64 pack2(float lo, float hi) {
    u64 r; asm("mov.b64 %0, {%1, %2};" : "=l"(r) : "f"(lo), "f"(hi)); return r;
}
__device__ __forceinline__ void unpack2(u64 v, float& lo, float& hi) {
    asm("mov.b64 {%0, %1}, %2;" : "=f"(lo), "=f"(hi) : "l"(v));
}
__device__ __forceinline__ u64 fma2(u64 a, u64 b, u64 c) {
    u64 d; asm("fma.rn.f32x2 %0, %1, %2, %3;" : "=l"(d) : "l"(a), "l"(b), "l"(c));
    return d;
}

// ---- fast exact-grade GELU ------------------------------------------------
// gelu(x) = 0.5x(1+erf(x/sqrt2)).  erf via Abramowitz-Stegun 7.1.26
// (|eps| <= 1.5e-7), branchless:  erf(t) = 1 - P(k) e^{-t^2}, k=1/(1+pt).
// gelu(x) = 0.5x + 0.5|x|*erf(|x|/sqrt2)   (odd-symmetry rewrite)
__device__ __forceinline__ float gelu_fast(float x) {
    const float p  = 0.3275911f;
    const float a1 = 0.254829592f, a2 = -0.284496736f, a3 = 1.421413741f,
                a4 = -1.453152027f, a5 = 1.061405429f;
    float ax = fabsf(x);
    float t  = ax * 0.70710678118654752440f;
    float d  = fmaf(p, t, 1.0f);
    float k;  asm("rcp.approx.ftz.f32 %0, %1;" : "=f"(k) : "f"(d));
    float P  = fmaf(a5, k, a4);
    P = fmaf(P, k, a3);
    P = fmaf(P, k, a2);
    P = fmaf(P, k, a1);
    P = P * k;
    float e  = __expf(-t * t);
    float E  = fmaf(-P, e, 1.0f);          // erf(t), t >= 0
    return fmaf(0.5f * ax, E, 0.5f * x);
}

// ---------------------------------------------------------------------------
// Kernel 1: A[i][c] = [coords_i, feat_i] @ W1 + b1
// 64 points / block. Thread (pg, q): 4 points x channel chunk q*4.
// ---------------------------------------------------------------------------
__global__ __launch_bounds__(THREADS, 4)
void compute_A_kernel(const float* __restrict__ coords,
                      const float* __restrict__ features,
                      const float* __restrict__ W1,
                      const float* __restrict__ b1,
                      int N) {
    __shared__ float W1s[DIN * COUT];   // [j][c] flat
    __shared__ float xsT[DIN][68];      // [j][point], padded

    const int t  = threadIdx.x;
    const int i0 = blockIdx.x * PTS;
    const int q  = t & 15;
    const int pg = t >> 4;

    {
        const float4* src = (const float4*)W1;
        float4* dst = (float4*)W1s;
        for (int e = t; e < (DIN * COUT) / 4; e += THREADS) dst[e] = src[e];
    }
    {
        int c  = t & 63;
        int p0 = t >> 6;
        #pragma unroll
        for (int rr = 0; rr < 16; ++rr) {
            int pt = p0 * 16 + rr;
            if (i0 + pt < N)
                xsT[3 + c][pt] = features[(size_t)(i0 + pt) * CIN + c];
        }
    }
    if (t < PTS * 3) {
        int pt = t / 3, d = t - pt * 3;
        if (i0 + pt < N) xsT[d][pt] = coords[(size_t)(i0 + pt) * 3 + d];
    }
    __syncthreads();

    u64 accLo[4], accHi[4];
    {
        float4 bb = ((const float4*)b1)[q];
        u64 blo = pack2(bb.x, bb.y), bhi = pack2(bb.z, bb.w);
        #pragma unroll
        for (int r = 0; r < 4; ++r) { accLo[r] = blo; accHi[r] = bhi; }
    }

    #pragma unroll
    for (int j = 0; j < DIN; ++j) {
        float4 w = *(const float4*)(W1s + j * COUT + q * 4);
        u64 wlo = pack2(w.x, w.y), whi = pack2(w.z, w.w);
        float4 xv = *(const float4*)(&xsT[j][pg * 4]);
        u64 x0 = pack2(xv.x, xv.x);
        u64 x1 = pack2(xv.y, xv.y);
        u64 x2 = pack2(xv.z, xv.z);
        u64 x3 = pack2(xv.w, xv.w);
        accLo[0] = fma2(x0, wlo, accLo[0]);  accHi[0] = fma2(x0, whi, accHi[0]);
        accLo[1] = fma2(x1, wlo, accLo[1]);  accHi[1] = fma2(x1, whi, accHi[1]);
        accLo[2] = fma2(x2, wlo, accLo[2]);  accHi[2] = fma2(x2, whi, accHi[2]);
        accLo[3] = fma2(x3, wlo, accLo[3]);  accHi[3] = fma2(x3, whi, accHi[3]);
    }

    #pragma unroll
    for (int r = 0; r < 4; ++r) {
        int i = i0 + pg * 4 + r;
        if (i < N) {
            float o0, o1, o2, o3;
            unpack2(accLo[r], o0, o1);
            unpack2(accHi[r], o2, o3);
            *(float4*)(g_A + (size_t)i * COUT + q * 4) = make_float4(o0, o1, o2, o3);
        }
    }
}

// ---------------------------------------------------------------------------
// Kernel 2: fused gather + GELU + mean + epilogue GEMMs, 64 points / block.
// ---------------------------------------------------------------------------
#define SM_W2   0
#define SM_WS   4096
#define SM_HT   8192
#define SM_FT   12544
#define SM_CS   16896
#define SM_FLOATS 17088
#define K2_SMEM_BYTES (SM_FLOATS * 4 + 1024 * 4)   // 72448

__global__ __launch_bounds__(THREADS, 3)
void fused_main_kernel(const float* __restrict__ coords,
                       const float* __restrict__ features,
                       const int* __restrict__ idx,
                       const float* __restrict__ W1,
                       const float* __restrict__ W2,
                       const float* __restrict__ b2,
                       const float* __restrict__ Ws,
                       const float* __restrict__ bs,
                       float* __restrict__ out,
                       int N) {
    extern __shared__ float sm2[];
    float* W2s = sm2 + SM_W2;
    float* Wss = sm2 + SM_WS;
    float* hT  = sm2 + SM_HT;    // [channel][point], stride 68
    float* fT  = sm2 + SM_FT;    // [channel][point], stride 68
    float* cs  = sm2 + SM_CS;    // [point][3]
    int*   idxs = (int*)(sm2 + SM_FLOATS);

    const int t  = threadIdx.x;
    const int i0 = blockIdx.x * PTS;
    const int q  = t & 15;
    const int pg = t >> 4;

    // ---- staging -----------------------------------------------------------
    {
        const float4* s2 = (const float4*)W2;
        const float4* ss = (const float4*)Ws;
        float4* d2 = (float4*)W2s;
        float4* ds = (float4*)Wss;
        for (int e = t; e < (COUT * COUT) / 4; e += THREADS) {
            d2[e] = s2[e];
            ds[e] = ss[e];
        }
    }
    {
        int c  = t & 63;
        int p0 = t >> 6;
        #pragma unroll
        for (int rr = 0; rr < 16; ++rr) {
            int pt = p0 * 16 + rr;
            if (i0 + pt < N)
                fT[c * 68 + pt] = features[(size_t)(i0 + pt) * CIN + c];
            else
                fT[c * 68 + pt] = 0.0f;
        }
    }
    for (int e = t; e < PTS * KNB; e += THREADS) {
        int row = e >> 4;
        idxs[e] = (i0 + row < N) ? idx[(size_t)(i0 + row) * KNB + (e & 15)] : 0;
    }
    if (t < PTS * 3) {
        int pt = t / 3, d = t - pt * 3;
        if (i0 + pt < N) cs[pt * 3 + d] = coords[(size_t)(i0 + pt) * 3 + d];
    }
    __syncthreads();

    // ---- phase A: gather + GELU + mean ------------------------------------
    {
        const float4* W1v = (const float4*)W1;
        float4 w0 = __ldg(W1v + 0 * 16 + q);
        float4 w1 = __ldg(W1v + 1 * 16 + q);
        float4 w2 = __ldg(W1v + 2 * 16 + q);

        #pragma unroll
        for (int r = 0; r < 4; ++r) {
            int pl = pg * 4 + r;
            int i  = i0 + pl;
            float h0 = 0.f, h1 = 0.f, h2 = 0.f, h3 = 0.f;
            if (i < N) {
                float cx = cs[pl * 3 + 0], cy = cs[pl * 3 + 1], cz = cs[pl * 3 + 2];
                float bx = -(cx * w0.x + cy * w1.x + cz * w2.x);
                float by = -(cx * w0.y + cy * w1.y + cz * w2.y);
                float bz = -(cx * w0.z + cy * w1.z + cz * w2.z);
                float bw = -(cx * w0.w + cy * w1.w + cz * w2.w);
                float a0 = 0.f, a1 = 0.f, a2 = 0.f, a3 = 0.f;
                #pragma unroll
                for (int k = 0; k < KNB; ++k) {
                    int j = idxs[pl * KNB + k];
                    float4 a = *(const float4*)(g_A + (size_t)j * COUT + q * 4);
                    a0 += gelu_fast(a.x + bx);
                    a1 += gelu_fast(a.y + by);
                    a2 += gelu_fast(a.z + bz);
                    a3 += gelu_fast(a.w + bw);
                }
                const float inv = 1.0f / (float)KNB;
                h0 = a0 * inv; h1 = a1 * inv; h2 = a2 * inv; h3 = a3 * inv;
            }
            hT[(q * 4 + 0) * 68 + pl] = h0;
            hT[(q * 4 + 1) * 68 + pl] = h1;
            hT[(q * 4 + 2) * 68 + pl] = h2;
            hT[(q * 4 + 3) * 68 + pl] = h3;
        }
    }
    __syncthreads();

    // ---- phase B: out = Hbar @ W2 + f @ Ws + (b2+bs), packed f32x2 --------
    u64 accLo[4], accHi[4];
    {
        float4 bb2 = __ldg((const float4*)b2 + q);
        float4 bbs = __ldg((const float4*)bs + q);
        u64 olo = pack2(bb2.x + bbs.x, bb2.y + bbs.y);
        u64 ohi = pack2(bb2.z + bbs.z, bb2.w + bbs.w);
        #pragma unroll
        for (int r = 0; r < 4; ++r) { accLo[r] = olo; accHi[r] = ohi; }
    }

    #pragma unroll 8
    for (int j = 0; j < COUT; ++j) {
        float4 wv2 = *(const float4*)(W2s + j * COUT + q * 4);
        float4 wvs = *(const float4*)(Wss + j * COUT + q * 4);
        u64 w2lo = pack2(wv2.x, wv2.y), w2hi = pack2(wv2.z, wv2.w);
        u64 wslo = pack2(wvs.x, wvs.y), wshi = pack2(wvs.z, wvs.w);
        float4 h4 = *(const float4*)(hT + j * 68 + pg * 4);
        float4 f4 = *(const float4*)(fT + j * 68 + pg * 4);

        u64 hd, fd;
        hd = pack2(h4.x, h4.x); fd = pack2(f4.x, f4.x);
        accLo[0] = fma2(hd, w2lo, accLo[0]);  accHi[0] = fma2(hd, w2hi, accHi[0]);
        accLo[0] = fma2(fd, wslo, accLo[0]);  accHi[0] = fma2(fd, wshi, accHi[0]);
        hd = pack2(h4.y, h4.y); fd = pack2(f4.y, f4.y);
        accLo[1] = fma2(hd, w2lo, accLo[1]);  accHi[1] = fma2(hd, w2hi, accHi[1]);
        accLo[1] = fma2(fd, wslo, accLo[1]);  accHi[1] = fma2(fd, wshi, accHi[1]);
        hd = pack2(h4.z, h4.z); fd = pack2(f4.z, f4.z);
        accLo[2] = fma2(hd, w2lo, accLo[2]);  accHi[2] = fma2(hd, w2hi, accHi[2]);
        accLo[2] = fma2(fd, wslo, accLo[2]);  accHi[2] = fma2(fd, wshi, accHi[2]);
        hd = pack2(h4.w, h4.w); fd = pack2(f4.w, f4.w);
        accLo[3] = fma2(hd, w2lo, accLo[3]);  accHi[3] = fma2(hd, w2hi, accHi[3]);
        accLo[3] = fma2(fd, wslo, accLo[3]);  accHi[3] = fma2(fd, wshi, accHi[3]);
    }

    #pragma unroll
    for (int r = 0; r < 4; ++r) {
        int i = i0 + pg * 4 + r;
        if (i < N) {
            float o0, o1, o2, o3;
            unpack2(accLo[r], o0, o1);
            unpack2(accHi[r], o2, o3);
            *(float4*)(out + (size_t)i * COUT + q * 4) = make_float4(o0, o1, o2, o3);
        }
    }
}

// ---------------------------------------------------------------------------
// Launch
// ---------------------------------------------------------------------------
extern "C" void kernel_launch(void* const* d_in, const int* in_sizes, int n_in,
                              void* d_out, int out_size) {
    const float* coords   = (const float*)d_in[0];
    const float* features = (const float*)d_in[1];
    const int*   idx      = (const int*)d_in[2];
    const float* W1       = (const float*)d_in[3];
    const float* b1       = (const float*)d_in[4];
    const float* W2       = (const float*)d_in[5];
    const float* b2       = (const float*)d_in[6];
    const float* Ws       = (const float*)d_in[7];
    const float* bs       = (const float*)d_in[8];
    float*       out      = (float*)d_out;

    const int N = in_sizes[0] / 3;
    const int blocks = (N + PTS - 1) / PTS;

    static int attr_done = 0;
    if (!attr_done) {
        cudaFuncSetAttribute(fused_main_kernel,
                             cudaFuncAttributeMaxDynamicSharedMemorySize,
                             K2_SMEM_BYTES);
        attr_done = 1;
    }

    compute_A_kernel<<<blocks, THREADS>>>(coords, features, W1, b1, N);
    fused_main_kernel<<<blocks, THREADS, K2_SMEM_BYTES>>>(coords, features, idx,
                                                          W1, W2, b2, Ws, bs,
                                                          out, N);
}